// round 16
// baseline (speedup 1.0000x reference)
#include <cuda_runtime.h>
#include <cuda_fp16.h>
#include <math.h>

// ---------------------------------------------------------------------------
// f16-accumulate MMA + movmatrix wrappers (sm_75+/sm_80, fine on compute_103)
// ---------------------------------------------------------------------------
__device__ __forceinline__ void mmaf16_16816(unsigned* d, const unsigned* a,
                                             unsigned b0, unsigned b1,
                                             unsigned c0, unsigned c1) {
    asm volatile(
        "mma.sync.aligned.m16n8k16.row.col.f16.f16.f16.f16 "
        "{%0,%1}, {%2,%3,%4,%5}, {%6,%7}, {%8,%9};"
        : "=r"(d[0]), "=r"(d[1])
        : "r"(a[0]), "r"(a[1]), "r"(a[2]), "r"(a[3]),
          "r"(b0), "r"(b1), "r"(c0), "r"(c1));
}
__device__ __forceinline__ void mmaf16_1688(unsigned* d, const unsigned* a,
                                            unsigned b0,
                                            unsigned c0, unsigned c1) {
    asm volatile(
        "mma.sync.aligned.m16n8k8.row.col.f16.f16.f16.f16 "
        "{%0,%1}, {%2,%3}, {%4}, {%5,%6};"
        : "=r"(d[0]), "=r"(d[1])
        : "r"(a[0]), "r"(a[1]), "r"(b0), "r"(c0), "r"(c1));
}
__device__ __forceinline__ unsigned movmt(unsigned a) {
    unsigned d;
    asm("movmatrix.sync.aligned.m8n8.trans.b16 %0, %1;" : "=r"(d) : "r"(a));
    return d;
}
__device__ __forceinline__ __half2 tanh2(__half2 x) {
    unsigned xi = *reinterpret_cast<unsigned*>(&x), yi;
    asm("tanh.approx.f16x2 %0, %1;" : "=r"(yi) : "r"(xi));
    return *reinterpret_cast<__half2*>(&yi);
}
// sigmoid with the 0.5 pre-folded into the weights: sig(2y) = 0.5*tanh(y)+0.5
__device__ __forceinline__ __half2 sig2h(__half2 y) {
    const __half2 h05 = __float2half2_rn(0.5f);
    return __hfma2(tanh2(y), h05, h05);
}
__device__ __forceinline__ unsigned pack2(float lo, float hi) {
    __half2 h = __floats2half2_rn(lo, hi);
    return *reinterpret_cast<unsigned*>(&h);
}
__device__ __forceinline__ __half2 u2h(unsigned u) {
    return *reinterpret_cast<__half2*>(&u);
}
__device__ __forceinline__ unsigned h2u(__half2 h) {
    return *reinterpret_cast<unsigned*>(&h);
}
__device__ __forceinline__ unsigned smem_u32x(const void* p) {
    unsigned a;
    asm("{ .reg .u64 t; cvta.to.shared.u64 t, %1; cvt.u32.u64 %0, t; }"
        : "=r"(a) : "l"(p));
    return a;
}

#define MBAR_INIT(addr, cnt) \
    asm volatile("mbarrier.init.shared.b64 [%0], %1;" \
                 :: "r"(addr), "r"(cnt) : "memory")
#define MBAR_ARRIVE(addr) \
    asm volatile("mbarrier.arrive.shared.b64 _, [%0];" \
                 :: "r"(addr) : "memory")
__device__ __forceinline__ void mbar_wait(unsigned addr, unsigned parity) {
    asm volatile(
        "{\n\t"
        ".reg .pred P1;\n\t"
        "WL_%=:\n\t"
        "mbarrier.try_wait.parity.acquire.cta.shared::cta.b64 P1, [%0], %1, 0x989680;\n\t"
        "@P1 bra.uni WD_%=;\n\t"
        "bra.uni WL_%=;\n\t"
        "WD_%=:\n\t"
        "}"
        :: "r"(addr), "r"(parity) : "memory");
}

// ---- LUT sigmoid (no MUFU): sigma = 0.5 + sign(y) * lut[|y| bit-bucket] ----
static constexpr int LUT_N = 4420;
__device__ __forceinline__ __half2 sig_lut(unsigned yu,
                                           const unsigned short* lut) {
    unsigned au = yu & 0x7FFF7FFFu;                  // |y| per half
    __half2 a = *reinterpret_cast<__half2*>(&au);
    a = __hmin2(a, __float2half2_rn(4.99f));         // clamp below 5.0
    unsigned ac = *reinterpret_cast<unsigned*>(&a);
    unsigned i0 = (ac >> 2) & 0x3FFFu;               // low-half bits[2:16)
    unsigned i1 = ac >> 18;                          // high-half bits[2:16)
    unsigned r = (unsigned)lut[i0] | ((unsigned)lut[i1] << 16);
    r |= (yu & 0x80008000u);                         // apply sign -> +-0.5*tanh
    return __hadd2(*reinterpret_cast<__half2*>(&r), __float2half2_rn(0.5f));
}

// ---------------------------------------------------------------------------
// 4-way gate/unit-split fused LSTM. CTA = 4 warps / 8 batch rows.
// Warp p owns units [8p,8p+8) for ALL 4 gates as 2 m-tiles:
//   tile0 rows = [i-gate units | f-gate units], tile1 = [g | o]
//   -> thread (gid,q) holds i,f,g,o of unit 8p+gid for batch {2q,2q+1}
//   -> 6 MMAs + 1-slot epilogue (3 MUFU tanh2 + 2 LUT sigmoids) per step.
// h exchange: each warp publishes ONE movmatrix fragment (8 k-rows);
// steps are paced by a 2-slot mbarrier (count=128) split-barrier pipeline.
// 2048 CTAs x 4 warps = 56 warps/SM, single wave.
// ---------------------------------------------------------------------------
__global__ void __launch_bounds__(128, 14) lstm_fused(
    const float* __restrict__ x,
    const int* __restrict__ mat_idx, const int* __restrict__ freq_idx,
    const float* __restrict__ W_ih, const float* __restrict__ W_hh,
    const float* __restrict__ b_ih, const float* __restrict__ b_hh,
    const float* __restrict__ mat_emb, const float* __restrict__ freq_emb,
    const float* __restrict__ fc_w, const float* __restrict__ fc_b,
    float* __restrict__ out, int T)
{
    __shared__ unsigned sx[2][4][32];       // [slot][warp][lane] h-frags
    __shared__ float sred[4][4][2];         // fc partials [warp][q][lo/hi]
    __shared__ unsigned s_xh[16][36];       // [xslot][step] packed x (pad)
    __shared__ unsigned short slut[LUT_N];  // sigmoid LUT (0.5*tanh|x|)
    __shared__ __align__(8) unsigned long long mbar[2];

    const int tid  = threadIdx.x;
    const int wid  = tid >> 5, lane = tid & 31;
    const int q    = lane & 3;            // batch col-pair selector
    const int gid  = lane >> 2;           // unit-in-warp / frag row

    const long long rowbase = (long long)blockIdx.x * 8;
    const unsigned mb0 = smem_u32x(&mbar[0]);

    // ---- fill sigmoid LUT (one-time; accurate tanhf) ----
    for (int j = tid; j < LUT_N; j += 128) {
        unsigned short bits = (unsigned short)((j << 2) | 2);
        __half hx = *reinterpret_cast<__half*>(&bits);
        float v = 0.5f * tanhf(__half2float(hx));
        __half hv = __float2half_rn(v);
        slut[j] = *reinterpret_cast<unsigned short*>(&hv);
    }
    if (tid == 0) { MBAR_INIT(mb0, 128); MBAR_INIT(mb0 + 8, 128); }
    sx[1][wid][lane] = 0u;                  // t=0 reads zeros from slot 1

    // ---- stationary weights: 2 m-tiles (i/f and g/o) for own 8 units ----
    // 0.5 folded into sigmoid gates i (n<32), f ([32,64)), o ([96,128)).
    auto wval = [&](int n, int k) -> float {
        float v;
        if (k < 32)       v = W_hh[n * 32 + k];
        else if (k < 35)  v = W_ih[n * 3 + (k - 32)];
        else if (k == 35) v = b_ih[n] + b_hh[n];
        else              v = 0.f;
        if (n < 64 || n >= 96) v *= 0.5f;   // i,f,o scaled; g untouched
        return v;
    };
    unsigned af[2][2][4];   // m-tile, k16-chunk, frag
    unsigned af2[2][2];     // k8 chunk (x + bias)
#pragma unroll
    for (int mt = 0; mt < 2; ++mt) {
        int n0 = mt * 64 + 8 * wid + gid;   // tile0: i ; tile1: g
        int n1 = n0 + 32;                   // tile0: f ; tile1: o
#pragma unroll
        for (int kc = 0; kc < 2; ++kc) {
            int k0 = 16 * kc + 2 * q;
            af[mt][kc][0] = pack2(wval(n0, k0),     wval(n0, k0 + 1));
            af[mt][kc][1] = pack2(wval(n1, k0),     wval(n1, k0 + 1));
            af[mt][kc][2] = pack2(wval(n0, k0 + 8), wval(n0, k0 + 9));
            af[mt][kc][3] = pack2(wval(n1, k0 + 8), wval(n1, k0 + 9));
        }
        int k2 = 32 + 2 * q;
        af2[mt][0] = pack2(wval(n0, k2), wval(n0, k2 + 1));
        af2[mt][1] = pack2(wval(n1, k2), wval(n1, k2 + 1));
    }

    // ---- x staging: threads 0..63 stage 8 rows x 32 steps per chunk ----
    const int xr = tid >> 3, xseg = tid & 7;     // valid for tid < 64
    const float4* xsrc =
        reinterpret_cast<const float4*>(x + (size_t)(rowbase + (xr & 7)) * T * 3)
        + xseg * 3;

    // ---- loop-carried state ----
    __half2 cst = __float2half2_rn(0.f);
    __half2 hv  = __float2half2_rn(0.f);

    __syncthreads();                        // LUT + mbar init + sx zero
    MBAR_ARRIVE(mb0 + 8);                   // prime slot-1 phase 0

    const bool xlane = (q < 2);
    const unsigned* xrd = &s_xh[gid * 2 + q][0];   // this lane's x slot row

    for (int tc = 0; tc < T; tc += 32) {
        __syncthreads();                    // prev chunk's step-31 reads done
        if (tid < 64) {
            const float4* src = xsrc + (tc >> 5) * 24;   // 96 floats/chunk/row
            float4 v0 = src[0], v1 = src[1], v2 = src[2];
            float f[12] = {v0.x, v0.y, v0.z, v0.w, v1.x, v1.y, v1.z, v1.w,
                           v2.x, v2.y, v2.z, v2.w};
#pragma unroll
            for (int k = 0; k < 4; ++k) {
                s_xh[xr * 2 + 0][xseg * 4 + k] = pack2(f[3 * k], f[3 * k + 1]);
                s_xh[xr * 2 + 1][xseg * 4 + k] = pack2(f[3 * k + 2], 1.0f);
            }
        }
        __syncthreads();

#pragma unroll 4
        for (int tl = 0; tl < 32; ++tl) {
            const int pub = tl & 1;
            const unsigned par = (unsigned)((tl >> 1) & 1);
            const unsigned b2 = xlane ? xrd[tl] : 0u;

            // ---- pre-wait: x-projection (h-independent) ----
            unsigned acc[2][2];
            mmaf16_1688(acc[0], af2[0], b2, 0u, 0u);
            mmaf16_1688(acc[1], af2[1], b2, 0u, 0u);

            // ---- wait for all warps' h(t-1) fragments ----
            mbar_wait(mb0 + 8 * (1 - pub), par);
            const unsigned w0 = sx[1 - pub][0][lane];
            const unsigned w1 = sx[1 - pub][1][lane];
            const unsigned w2 = sx[1 - pub][2][lane];
            const unsigned w3 = sx[1 - pub][3][lane];
            mmaf16_16816(acc[0], af[0][0], w0, w1, acc[0][0], acc[0][1]);
            mmaf16_16816(acc[1], af[1][0], w0, w1, acc[1][0], acc[1][1]);
            mmaf16_16816(acc[0], af[0][1], w2, w3, acc[0][0], acc[0][1]);
            mmaf16_16816(acc[1], af[1][1], w2, w3, acc[1][0], acc[1][1]);

            // ---- 1-slot LSTM update: i,o via LUT; f,g,tanh(c) on MUFU ----
            __half2 si = sig_lut(acc[0][0], slut);
            __half2 sf = sig2h(u2h(acc[0][1]));
            __half2 tg = tanh2(u2h(acc[1][0]));
            __half2 so = sig_lut(acc[1][1], slut);
            __half2 cc = __hfma2(sf, cst, __hmul2(si, tg));
            cst = cc;
            hv = __hmul2(so, tanh2(cc));

            // ---- publish own fragment, arrive (non-blocking) ----
            sx[pub][wid][lane] = movmt(h2u(hv));
            MBAR_ARRIVE(mb0 + 8 * pub);
        }
    }

    // ---- fc head: partial for unit 8*wid+gid, reduce over gid + warps ----
    float w = fc_w[8 * wid + gid];
    float p_lo = __low2float(hv) * w;     // batch row rowbase + 2q
    float p_hi = __high2float(hv) * w;    // batch row rowbase + 2q+1
#pragma unroll
    for (int off = 4; off < 32; off <<= 1) {
        p_lo += __shfl_xor_sync(0xFFFFFFFFu, p_lo, off);
        p_hi += __shfl_xor_sync(0xFFFFFFFFu, p_hi, off);
    }
    if (lane < 4) { sred[wid][q][0] = p_lo; sred[wid][q][1] = p_hi; }
    __syncthreads();
    if (tid < 4) {
        float base = fc_b[0];
#pragma unroll
        for (int k = 0; k < 2; ++k) {
            long long r = rowbase + 2 * tid + k;
            float s = sred[0][tid][k] + sred[1][tid][k]
                    + sred[2][tid][k] + sred[3][tid][k] + base;
            int mi = mat_idx[r], fi = freq_idx[r];
#pragma unroll
            for (int e = 0; e < 4; ++e) s += mat_emb[mi * 4 + e] * fc_w[32 + e];
#pragma unroll
            for (int e = 0; e < 2; ++e) s += freq_emb[fi * 2 + e] * fc_w[36 + e];
            out[r] = s;
        }
    }
}

extern "C" void kernel_launch(void* const* d_in, const int* in_sizes, int n_in,
                              void* d_out, int out_size) {
    const float* x        = (const float*)d_in[0];
    const int*   mat_idx  = (const int*)  d_in[1];
    const int*   freq_idx = (const int*)  d_in[2];
    const float* W_ih     = (const float*)d_in[3];
    const float* W_hh     = (const float*)d_in[4];
    const float* b_ih     = (const float*)d_in[5];
    const float* b_hh     = (const float*)d_in[6];
    const float* mat_emb  = (const float*)d_in[7];
    const float* freq_emb = (const float*)d_in[8];
    const float* fc_w     = (const float*)d_in[9];
    const float* fc_b     = (const float*)d_in[10];

    int B = in_sizes[1];                  // mat_idx has B elements
    int T = in_sizes[0] / (B * 3);        // x has B*T*3 elements
    int grid = B / 8;                     // 8 rows per 4-warp CTA

    lstm_fused<<<grid, 128>>>(x, mat_idx, freq_idx, W_ih, W_hh, b_ih, b_hh,
                              mat_emb, freq_emb, fc_w, fc_b,
                              (float*)d_out, T);
}

// round 17
// speedup vs baseline: 1.3264x; 1.3264x over previous
#include <cuda_runtime.h>
#include <cuda_fp16.h>
#include <math.h>

// ---------------------------------------------------------------------------
// f16-accumulate MMA + movmatrix wrappers (sm_75+/sm_80, fine on compute_103)
// ---------------------------------------------------------------------------
__device__ __forceinline__ void mmaf16_16816(unsigned* d, const unsigned* a,
                                             unsigned b0, unsigned b1,
                                             unsigned c0, unsigned c1) {
    asm volatile(
        "mma.sync.aligned.m16n8k16.row.col.f16.f16.f16.f16 "
        "{%0,%1}, {%2,%3,%4,%5}, {%6,%7}, {%8,%9};"
        : "=r"(d[0]), "=r"(d[1])
        : "r"(a[0]), "r"(a[1]), "r"(a[2]), "r"(a[3]),
          "r"(b0), "r"(b1), "r"(c0), "r"(c1));
}
__device__ __forceinline__ void mmaf16_1688(unsigned* d, const unsigned* a,
                                            unsigned b0,
                                            unsigned c0, unsigned c1) {
    asm volatile(
        "mma.sync.aligned.m16n8k8.row.col.f16.f16.f16.f16 "
        "{%0,%1}, {%2,%3}, {%4}, {%5,%6};"
        : "=r"(d[0]), "=r"(d[1])
        : "r"(a[0]), "r"(a[1]), "r"(b0), "r"(c0), "r"(c1));
}
__device__ __forceinline__ unsigned movmt(unsigned a) {
    unsigned d;
    asm("movmatrix.sync.aligned.m8n8.trans.b16 %0, %1;" : "=r"(d) : "r"(a));
    return d;
}
__device__ __forceinline__ __half2 tanh2(__half2 x) {
    unsigned xi = *reinterpret_cast<unsigned*>(&x), yi;
    asm("tanh.approx.f16x2 %0, %1;" : "=r"(yi) : "r"(xi));
    return *reinterpret_cast<__half2*>(&yi);
}
// sigmoid with the 0.5 pre-folded into the weights: sig(2y) = 0.5*tanh(y)+0.5
__device__ __forceinline__ __half2 sig2h(__half2 y) {
    const __half2 h05 = __float2half2_rn(0.5f);
    return __hfma2(tanh2(y), h05, h05);
}
__device__ __forceinline__ unsigned pack2(float lo, float hi) {
    __half2 h = __floats2half2_rn(lo, hi);
    return *reinterpret_cast<unsigned*>(&h);
}
__device__ __forceinline__ __half2 u2h(unsigned u) {
    return *reinterpret_cast<__half2*>(&u);
}
__device__ __forceinline__ unsigned smem_u32x(const void* p) {
    unsigned a;
    asm("{ .reg .u64 t; cvta.to.shared.u64 t, %1; cvt.u32.u64 %0, t; }"
        : "=r"(a) : "l"(p));
    return a;
}

// ---- per-lane release/acquire flag sync (replaces mbarrier) ----
__device__ __forceinline__ void flag_publish(unsigned addr, int v) {
    asm volatile("st.release.cta.shared.b32 [%0], %1;"
                 :: "r"(addr), "r"(v) : "memory");
}
__device__ __forceinline__ void flag_wait(unsigned addr, int target) {
    asm volatile(
        "{\n\t"
        ".reg .pred P;\n\t"
        ".reg .s32 v;\n\t"
        "FW_%=:\n\t"
        "ld.acquire.cta.shared.b32 v, [%0];\n\t"
        "setp.lt.s32 P, v, %1;\n\t"
        "@P bra FW_%=;\n\t"
        "}"
        :: "r"(addr), "r"(target) : "memory");
}

// ---- LUT sigmoid (no MUFU): sigma = 0.5 + sign(y) * lut[|y| bit-bucket] ----
static constexpr int LUT_N = 4420;
__device__ __forceinline__ __half2 sig_lut(unsigned yu,
                                           const unsigned short* lut) {
    unsigned au = yu & 0x7FFF7FFFu;                  // |y| per half
    __half2 a = *reinterpret_cast<__half2*>(&au);
    a = __hmin2(a, __float2half2_rn(4.99f));         // clamp below 5.0
    unsigned ac = *reinterpret_cast<unsigned*>(&a);
    unsigned i0 = (ac >> 2) & 0x3FFFu;               // low-half bits[2:16)
    unsigned i1 = ac >> 18;                          // high-half bits[2:16)
    unsigned r = (unsigned)lut[i0] | ((unsigned)lut[i1] << 16);
    r |= (yu & 0x80008000u);                         // apply sign -> +-0.5*tanh
    return __hadd2(*reinterpret_cast<__half2*>(&r), __float2half2_rn(0.5f));
}

// ---------------------------------------------------------------------------
// Gate-split fused LSTM (R15 structure). R17: inter-warp step sync via
// per-lane monotonic flags (st.release / ld.acquire polling) instead of
// mbarrier — pairwise lane L -> lane L visibility is all the exchange needs,
// and the acquire-poll costs ~30 cy when ready vs try_wait's 60-90.
// Pipeline: epilogue -> movmt -> STS data -> st.release flag(ts+1) ->
// [next step: x-proj k8 MMAs + OWN-half k16 MMAs] -> acquire-poll partner
// flag >= ts -> LDS partner -> 4 partner MMAs -> epilogue.
// ---------------------------------------------------------------------------
__global__ void __launch_bounds__(64, 14) lstm_fused(
    const float* __restrict__ x,
    const int* __restrict__ mat_idx, const int* __restrict__ freq_idx,
    const float* __restrict__ W_ih, const float* __restrict__ W_hh,
    const float* __restrict__ b_ih, const float* __restrict__ b_hh,
    const float* __restrict__ mat_emb, const float* __restrict__ freq_emb,
    const float* __restrict__ fc_w, const float* __restrict__ fc_b,
    float* __restrict__ out, int T)
{
    __shared__ unsigned long long sx[2][2][32];  // [slot][warp][lane] h-frags
    __shared__ unsigned sfl[2][32];              // [warp][lane] step flags
    __shared__ float sred[2][4][2];              // fc partials
    __shared__ unsigned s_xh[16][36];            // [xslot][step] packed x (pad)
    __shared__ unsigned short slut[LUT_N];       // sigmoid LUT (0.5*tanh|x|)

    const int tid  = threadIdx.x;
    const int wid  = tid >> 5, lane = tid & 31;
    const int q    = lane & 3;            // batch col-pair selector
    const int gid  = lane >> 2;           // row-in-tile

    const long long rowbase = (long long)blockIdx.x * 8;

    // ---- fill sigmoid LUT (one-time; accurate tanhf) ----
    for (int j = tid; j < LUT_N; j += 64) {
        unsigned short bits = (unsigned short)((j << 2) | 2);
        __half hx = *reinterpret_cast<__half*>(&bits);
        float v = 0.5f * tanhf(__half2float(hx));
        __half hv = __float2half_rn(v);
        slut[j] = *reinterpret_cast<unsigned short*>(&hv);
    }
    sfl[wid][lane] = 0u;                    // flags start at 0
    sx[1][wid][lane] = 0ull;                // t=0 reads zeros from slot 1

    const unsigned fl_own  = smem_u32x(&sfl[wid][lane]);
    const unsigned fl_part = smem_u32x(&sfl[wid ^ 1][lane]);

    // ---- stationary A fragments; 0.5 folded into sigmoid gates (i,f,o);
    //      chunk0 = OWN k-cols [16*wid,+16), chunk1 = partner's ----
    auto wval = [&](int n, int k) -> float {
        float v;
        if (k < 32)       v = W_hh[n * 32 + k];
        else if (k < 35)  v = W_ih[n * 3 + (k - 32)];
        else if (k == 35) v = b_ih[n] + b_hh[n];
        else              v = 0.f;
        if ((n >> 5) != 2) v *= 0.5f;      // gates i,f,o scaled; g untouched
        return v;
    };
    unsigned af[4][2][4];   // gate, chunk(own/partner), frag
    unsigned af2[4][2];     // k8 chunk (x + bias)
#pragma unroll
    for (int g = 0; g < 4; ++g) {
        int n0 = g * 32 + 16 * wid + gid, n1 = n0 + 8;
#pragma unroll
        for (int kc = 0; kc < 2; ++kc) {
            int k0 = 16 * ((kc == 0) ? wid : (1 - wid)) + 2 * q;
            af[g][kc][0] = pack2(wval(n0, k0),     wval(n0, k0 + 1));
            af[g][kc][1] = pack2(wval(n1, k0),     wval(n1, k0 + 1));
            af[g][kc][2] = pack2(wval(n0, k0 + 8), wval(n0, k0 + 9));
            af[g][kc][3] = pack2(wval(n1, k0 + 8), wval(n1, k0 + 9));
        }
        int k2 = 32 + 2 * q;
        af2[g][0] = pack2(wval(n0, k2), wval(n0, k2 + 1));
        af2[g][1] = pack2(wval(n1, k2), wval(n1, k2 + 1));
    }

    // ---- x staging setup: thread (xr=tid>>3, xseg=tid&7) handles 4 steps ----
    const int xr = tid >> 3, xseg = tid & 7;
    const float4* xsrc =
        reinterpret_cast<const float4*>(x + (size_t)(rowbase + xr) * T * 3)
        + xseg * 3;                        // 12 floats = steps 4*xseg..+4

    // ---- loop-carried state ----
    __half2 cst[2];
    cst[0] = __float2half2_rn(0.f);
    cst[1] = __float2half2_rn(0.f);
    unsigned hs[2];
    hs[0] = hs[1] = 0u;
    unsigned f0 = 0u, f1 = 0u;             // own h fragments (t=0: zero)

    __syncthreads();                       // LUT + flags + sx zero visible

    const bool xlane = (q < 2);
    const unsigned* xrd = &s_xh[gid * 2 + q][0];   // this lane's x slot row

    for (int tc = 0; tc < T; tc += 32) {
        // ---- stage chunk: 3x LDG.128, pre-pack to half2, STS ----
        {
            const float4* src = xsrc + (tc >> 5) * 24;   // 96 floats/chunk/row
            float4 v0 = src[0], v1 = src[1], v2 = src[2];
            float f[12] = {v0.x, v0.y, v0.z, v0.w, v1.x, v1.y, v1.z, v1.w,
                           v2.x, v2.y, v2.z, v2.w};
#pragma unroll
            for (int k = 0; k < 4; ++k) {
                s_xh[xr * 2 + 0][xseg * 4 + k] = pack2(f[3 * k], f[3 * k + 1]);
                s_xh[xr * 2 + 1][xseg * 4 + k] = pack2(f[3 * k + 2], 1.0f);
            }
        }
        __syncthreads();

        for (int t4 = 0; t4 < 32; t4 += 4) {
            // x for 4 steps: one LDS.128 (slot stride 36 words)
            uint4 xv = make_uint4(0u, 0u, 0u, 0u);
            if (xlane) xv = *reinterpret_cast<const uint4*>(xrd + t4);

#pragma unroll
            for (int k = 0; k < 4; ++k) {
                const int tl = t4 + k;
                const int ts = tc + tl;                // global step index
                const int pub = tl & 1;                // publish slot
                const unsigned b2 = (k == 0) ? xv.x : (k == 1) ? xv.y
                                  : (k == 2) ? xv.z : xv.w;

                // ---- pre-wait: x-projection + OWN-half MMAs ----
                unsigned acc[4][2];
#pragma unroll
                for (int g = 0; g < 4; ++g)
                    mmaf16_1688(acc[g], af2[g], b2, 0u, 0u);
#pragma unroll
                for (int g = 0; g < 4; ++g)
                    mmaf16_16816(acc[g], af[g][0], f0, f1,
                                 acc[g][0], acc[g][1]);

                // ---- acquire-poll partner's h(t-1) publish ----
                flag_wait(fl_part, ts);
                const unsigned long long w = sx[1 - pub][wid ^ 1][lane];
#pragma unroll
                for (int g = 0; g < 4; ++g)
                    mmaf16_16816(acc[g], af[g][1],
                                 (unsigned)w, (unsigned)(w >> 32),
                                 acc[g][0], acc[g][1]);

                // ---- LSTM update (3 LUT sigmoids, 7 MUFU tanh2) ----
                {
                    __half2 si = sig_lut(acc[0][0], slut);
                    __half2 so = sig_lut(acc[3][0], slut);
                    __half2 sf = sig2h(u2h(acc[1][0]));
                    __half2 tg = tanh2(u2h(acc[2][0]));
                    __half2 cc = __hfma2(sf, cst[0], __hmul2(si, tg));
                    cst[0] = cc;
                    __half2 hv = __hmul2(so, tanh2(cc));
                    hs[0] = *reinterpret_cast<unsigned*>(&hv);
                }
                {
                    __half2 si = sig_lut(acc[0][1], slut);
                    __half2 sf = sig2h(u2h(acc[1][1]));
                    __half2 tg = tanh2(u2h(acc[2][1]));
                    __half2 so = sig2h(u2h(acc[3][1]));
                    __half2 cc = __hfma2(sf, cst[1], __hmul2(si, tg));
                    cst[1] = cc;
                    __half2 hv = __hmul2(so, tanh2(cc));
                    hs[1] = *reinterpret_cast<unsigned*>(&hv);
                }

                // ---- publish own fragments (release flag = ts+1) ----
                f0 = movmt(hs[0]);     // own k-rows [16*wid, 16*wid+8)
                f1 = movmt(hs[1]);     // own k-rows [16*wid+8, 16*wid+16)
                sx[pub][wid][lane] =
                    (unsigned long long)f0 | ((unsigned long long)f1 << 32);
                flag_publish(fl_own, ts + 1);
            }
        }
    }

    // ---- fc head: partial over this warp's 16 units, then pair-reduce ----
    float p_lo = 0.f, p_hi = 0.f;          // batch rows rowbase+2q, +2q+1
#pragma unroll
    for (int s = 0; s < 2; ++s) {
        __half2 hv = u2h(hs[s]);
        float w = fc_w[16 * wid + 8 * s + gid];
        p_lo = fmaf(__low2float(hv),  w, p_lo);
        p_hi = fmaf(__high2float(hv), w, p_hi);
    }
#pragma unroll
    for (int off = 4; off < 32; off <<= 1) {
        p_lo += __shfl_xor_sync(0xFFFFFFFFu, p_lo, off);
        p_hi += __shfl_xor_sync(0xFFFFFFFFu, p_hi, off);
    }
    if (lane < 4) { sred[wid][q][0] = p_lo; sred[wid][q][1] = p_hi; }
    __syncthreads();
    if (tid < 4) {
        float base = fc_b[0];
#pragma unroll
        for (int k = 0; k < 2; ++k) {
            long long r = rowbase + 2 * tid + k;
            float s = sred[0][tid][k] + sred[1][tid][k] + base;
            int mi = mat_idx[r], fi = freq_idx[r];
#pragma unroll
            for (int e = 0; e < 4; ++e) s += mat_emb[mi * 4 + e] * fc_w[32 + e];
#pragma unroll
            for (int e = 0; e < 2; ++e) s += freq_emb[fi * 2 + e] * fc_w[36 + e];
            out[r] = s;
        }
    }
}

extern "C" void kernel_launch(void* const* d_in, const int* in_sizes, int n_in,
                              void* d_out, int out_size) {
    const float* x        = (const float*)d_in[0];
    const int*   mat_idx  = (const int*)  d_in[1];
    const int*   freq_idx = (const int*)  d_in[2];
    const float* W_ih     = (const float*)d_in[3];
    const float* W_hh     = (const float*)d_in[4];
    const float* b_ih     = (const float*)d_in[5];
    const float* b_hh     = (const float*)d_in[6];
    const float* mat_emb  = (const float*)d_in[7];
    const float* freq_emb = (const float*)d_in[8];
    const float* fc_w     = (const float*)d_in[9];
    const float* fc_b     = (const float*)d_in[10];

    int B = in_sizes[1];                  // mat_idx has B elements
    int T = in_sizes[0] / (B * 3);        // x has B*T*3 elements
    int grid = B / 8;                     // 8 rows per 2-warp CTA

    lstm_fused<<<grid, 64>>>(x, mat_idx, freq_idx, W_ih, W_hh, b_ih, b_hh,
                             mat_emb, freq_emb, fc_w, fc_b,
                             (float*)d_out, T);
}